// round 1
// baseline (speedup 1.0000x reference)
#include <cuda_runtime.h>
#include <cuda_bf16.h>

// Problem constants
#define B_  64
#define T_  1024
#define D_  512
#define H_  512
#define O_  128
#define HALF_ 256
#define M_  (B_ * T_)          // 65536 rows
#define BH_ (B_ * H_)          // 32768

// Scratch in device globals (no allocation allowed)
__device__ float g_d1[T_ * B_ * H_];    // [T,B,H] raw branch-1 GEMM result (no bias)
__device__ float g_d2[T_ * B_ * H_];    // [T,B,H]
__device__ float g_mems[T_ * B_ * H_];  // [T,B,H]

// ---------------------------------------------------------------------------
// Kernel 1: dual GEMM.
//   d1[t,b,h] = sum_{k<256} x[b,t,k]     * w1[h,k]
//   d2[t,b,h] = sum_{k<256} x[b,t,256+k] * w2[h,k]
// Tile: 64(M) x 64(N=h), BK=16, 256 threads, 4x4 micro-tile per thread,
// two accumulator sets (d1, d2) over the two K phases.
// ---------------------------------------------------------------------------
#define BM 64
#define BN 64
#define BK 16

__global__ __launch_bounds__(256)
void dual_gemm_kernel(const float* __restrict__ x,
                      const float* __restrict__ w1,
                      const float* __restrict__ w2)
{
    __shared__ float As[BK][BM];
    __shared__ float Bs[BK][BN];

    const int tid   = threadIdx.x;
    const int m0    = blockIdx.x * BM;
    const int n0    = blockIdx.y * BN;

    const int lrow  = tid >> 2;         // 0..63
    const int lcol  = (tid & 3) * 4;    // 0,4,8,12

    const int tm    = (tid >> 4) * 4;   // 0..60
    const int tn    = (tid & 15) * 4;   // 0..60

    float acc1[4][4] = {};
    float acc2[4][4] = {};

#define GEMM_PHASE(WPTR, KBASE, ACC)                                            \
    for (int kk = 0; kk < HALF_; kk += BK) {                                    \
        float4 av = *(const float4*)(x + (size_t)(m0 + lrow) * D_ + (KBASE) + kk + lcol); \
        As[lcol + 0][lrow] = av.x;                                              \
        As[lcol + 1][lrow] = av.y;                                              \
        As[lcol + 2][lrow] = av.z;                                              \
        As[lcol + 3][lrow] = av.w;                                              \
        float4 bv = *(const float4*)((WPTR) + (size_t)(n0 + lrow) * HALF_ + kk + lcol); \
        Bs[lcol + 0][lrow] = bv.x;                                              \
        Bs[lcol + 1][lrow] = bv.y;                                              \
        Bs[lcol + 2][lrow] = bv.z;                                              \
        Bs[lcol + 3][lrow] = bv.w;                                              \
        __syncthreads();                                                        \
        _Pragma("unroll")                                                       \
        for (int k = 0; k < BK; ++k) {                                          \
            float4 a4 = *(const float4*)&As[k][tm];                             \
            float4 b4 = *(const float4*)&Bs[k][tn];                             \
            float a[4] = {a4.x, a4.y, a4.z, a4.w};                              \
            float b[4] = {b4.x, b4.y, b4.z, b4.w};                              \
            _Pragma("unroll")                                                   \
            for (int i = 0; i < 4; ++i)                                         \
                _Pragma("unroll")                                               \
                for (int j = 0; j < 4; ++j)                                     \
                    ACC[i][j] += a[i] * b[j];                                   \
        }                                                                       \
        __syncthreads();                                                        \
    }

    GEMM_PHASE(w1, 0,     acc1)
    GEMM_PHASE(w2, HALF_, acc2)
#undef GEMM_PHASE

    // Epilogue: write [T,B,H] layout. m = b*T + t
    #pragma unroll
    for (int i = 0; i < 4; ++i) {
        const int m = m0 + tm + i;
        const int b = m >> 10;          // / T_
        const int t = m & (T_ - 1);
        const size_t base = (size_t)t * BH_ + (size_t)b * H_ + n0 + tn;
        float4 v1 = make_float4(acc1[i][0], acc1[i][1], acc1[i][2], acc1[i][3]);
        float4 v2 = make_float4(acc2[i][0], acc2[i][1], acc2[i][2], acc2[i][3]);
        *(float4*)(g_d1 + base) = v1;
        *(float4*)(g_d2 + base) = v2;
    }
}

// ---------------------------------------------------------------------------
// Kernel 2: sequential EMA scan over T. One thread per (b,h).
// ---------------------------------------------------------------------------
__global__ __launch_bounds__(256)
void scan_kernel(const float* __restrict__ b1, const float* __restrict__ tau1,
                 const float* __restrict__ b2, const float* __restrict__ tau2)
{
    const int idx = blockIdx.x * blockDim.x + threadIdx.x;   // 0..32767
    const int h   = idx & (H_ - 1);

    const float a1 = 1.0f / (1.0f + __expf(-tau1[h]));
    const float a2 = 1.0f / (1.0f + __expf(-tau2[h]));
    const float c1 = 1.0f - a1;
    const float c2 = 1.0f - a2;
    const float bb1 = b1[h];
    const float bb2 = b2[h];

    float d1 = 0.0f, d2 = 0.0f, mem = 0.0f;

    #pragma unroll 1
    for (int t = 0; t < T_; t += 8) {
        float i1[8], i2[8];
        #pragma unroll
        for (int u = 0; u < 8; ++u) {
            i1[u] = g_d1[(size_t)(t + u) * BH_ + idx];
            i2[u] = g_d2[(size_t)(t + u) * BH_ + idx];
        }
        #pragma unroll
        for (int u = 0; u < 8; ++u) {
            d1  = a1 * d1 + c1 * (i1[u] + bb1);
            d2  = a2 * d2 + c2 * (i2[u] + bb2);
            mem = 0.8f * mem + 0.2f * (d1 + d2);
            g_mems[(size_t)(t + u) * BH_ + idx] = mem;
        }
    }
}

// ---------------------------------------------------------------------------
// Kernel 3: output GEMM + sigmoid.
//   out[b,t,o] = sigmoid( sum_h mems[t,b,h] * wo[o,h] + bo[o] )
// mems flattened: row r = t*B + b, K = H = 512.
// ---------------------------------------------------------------------------
__global__ __launch_bounds__(256)
void out_gemm_kernel(const float* __restrict__ wo,
                     const float* __restrict__ bo,
                     float* __restrict__ out)
{
    __shared__ float As[BK][BM];
    __shared__ float Bs[BK][BN];

    const int tid  = threadIdx.x;
    const int m0   = blockIdx.x * BM;
    const int n0   = blockIdx.y * BN;

    const int lrow = tid >> 2;
    const int lcol = (tid & 3) * 4;

    const int tm   = (tid >> 4) * 4;
    const int tn   = (tid & 15) * 4;

    float acc[4][4] = {};

    for (int kk = 0; kk < H_; kk += BK) {
        float4 av = *(const float4*)(g_mems + (size_t)(m0 + lrow) * H_ + kk + lcol);
        As[lcol + 0][lrow] = av.x;
        As[lcol + 1][lrow] = av.y;
        As[lcol + 2][lrow] = av.z;
        As[lcol + 3][lrow] = av.w;
        float4 bv = *(const float4*)(wo + (size_t)(n0 + lrow) * H_ + kk + lcol);
        Bs[lcol + 0][lrow] = bv.x;
        Bs[lcol + 1][lrow] = bv.y;
        Bs[lcol + 2][lrow] = bv.z;
        Bs[lcol + 3][lrow] = bv.w;
        __syncthreads();
        #pragma unroll
        for (int k = 0; k < BK; ++k) {
            float4 a4 = *(const float4*)&As[k][tm];
            float4 b4 = *(const float4*)&Bs[k][tn];
            float a[4] = {a4.x, a4.y, a4.z, a4.w};
            float b[4] = {b4.x, b4.y, b4.z, b4.w};
            #pragma unroll
            for (int i = 0; i < 4; ++i)
                #pragma unroll
                for (int j = 0; j < 4; ++j)
                    acc[i][j] += a[i] * b[j];
        }
        __syncthreads();
    }

    // Epilogue: row m = t*B + b ; out[b*T*O + t*O + o] = sigmoid(acc + bo[o])
    #pragma unroll
    for (int i = 0; i < 4; ++i) {
        const int m = m0 + tm + i;
        const int t = m >> 6;          // / B_
        const int b = m & (B_ - 1);
        const int o = n0 + tn;
        float4 v;
        v.x = acc[i][0] + bo[o + 0];
        v.y = acc[i][1] + bo[o + 1];
        v.z = acc[i][2] + bo[o + 2];
        v.w = acc[i][3] + bo[o + 3];
        v.x = 1.0f / (1.0f + __expf(-v.x));
        v.y = 1.0f / (1.0f + __expf(-v.y));
        v.z = 1.0f / (1.0f + __expf(-v.z));
        v.w = 1.0f / (1.0f + __expf(-v.w));
        *(float4*)(out + (size_t)b * (T_ * O_) + (size_t)t * O_ + o) = v;
    }
}

// ---------------------------------------------------------------------------
extern "C" void kernel_launch(void* const* d_in, const int* in_sizes, int n_in,
                              void* d_out, int out_size)
{
    const float* x    = (const float*)d_in[0];
    const float* w1   = (const float*)d_in[1];
    const float* b1   = (const float*)d_in[2];
    const float* tau1 = (const float*)d_in[3];
    const float* w2   = (const float*)d_in[4];
    const float* b2   = (const float*)d_in[5];
    const float* tau2 = (const float*)d_in[6];
    const float* wo   = (const float*)d_in[7];
    const float* bo   = (const float*)d_in[8];
    float* out = (float*)d_out;

    dim3 g1(M_ / BM, H_ / BN);           // 1024 x 8
    dual_gemm_kernel<<<g1, 256>>>(x, w1, w2);

    scan_kernel<<<BH_ / 256, 256>>>(b1, tau1, b2, tau2);

    dim3 g3(M_ / BM, O_ / BN);           // 1024 x 2
    out_gemm_kernel<<<g3, 256>>>(wo, bo, out);
}

// round 2
// speedup vs baseline: 1.9391x; 1.9391x over previous
#include <cuda_runtime.h>
#include <cuda_bf16.h>

// Problem constants
#define B_    64
#define T_    1024
#define D_    512
#define H_    512
#define O_    128
#define HALF_ 256
#define M_    (B_ * T_)          // 65536 rows
#define BH_   (B_ * H_)          // 32768

// Scratch in device globals (no allocation allowed)
__device__ float g_d1[T_ * B_ * H_];    // [T,B,H]
__device__ float g_d2[T_ * B_ * H_];    // [T,B,H]
__device__ float g_mems[T_ * B_ * H_];  // [T,B,H]

// ---------------------------------------------------------------------------
// Packed fp32x2 helpers (sm_100+)
// ---------------------------------------------------------------------------
__device__ __forceinline__ unsigned long long pack2(float x, float y) {
    unsigned long long r;
    asm("mov.b64 %0, {%1, %2};" : "=l"(r) : "f"(x), "f"(y));
    return r;
}
__device__ __forceinline__ unsigned long long fma2(unsigned long long a,
                                                   unsigned long long b,
                                                   unsigned long long c) {
    unsigned long long d;
    asm("fma.rn.f32x2 %0, %1, %2, %3;" : "=l"(d) : "l"(a), "l"(b), "l"(c));
    return d;
}
__device__ __forceinline__ float2 unpack2(unsigned long long v) {
    float2 f;
    asm("mov.b64 {%0, %1}, %2;" : "=f"(f.x), "=f"(f.y) : "l"(v));
    return f;
}

// ---------------------------------------------------------------------------
// Shared 128x128 tile GEMM core, BK=8, 256 threads, 8x8 microtile, f32x2 FMA.
//   C[m0+.., n0+..] += A[m][k] * B[n][k]   (both row-major, K-contiguous)
// Warp layout: warp (w&1 -> m half 64, w>>1 -> n quarter 32),
// lane: m-lane = lane&7 (8 m positions), n-group = lane>>3 (4 n positions).
// ---------------------------------------------------------------------------
__device__ __forceinline__ void sgemm_tile_128(
    const float* __restrict__ Aptr, int ALD, int AOFF, int m0,
    const float* __restrict__ Bptr, int BLD, int BOFF, int n0,
    int K,
    unsigned long long acc[8][4],
    float* __restrict__ As, float* __restrict__ Bs)  // each [8][128]
{
    const int tid  = threadIdx.x;
    const int grow = tid >> 1;            // 0..127 (row within tile)
    const int gcol = (tid & 1) * 4;       // 0 or 4 (k offset)

    const float* ag = Aptr + (size_t)(m0 + grow) * ALD + AOFF + gcol;
    const float* bg = Bptr + (size_t)(n0 + grow) * BLD + BOFF + gcol;

    const int warp = tid >> 5, lane = tid & 31;
    const int wm = (warp & 1) * 64 + (lane & 7) * 8;
    const int wn = (warp >> 1) * 32 + (lane >> 3) * 8;

    float4 pa = *(const float4*)ag;
    float4 pb = *(const float4*)bg;

    const int iters = K >> 3;
    for (int kk = 0; kk < iters; ++kk) {
        As[(gcol + 0) * 128 + grow] = pa.x;
        As[(gcol + 1) * 128 + grow] = pa.y;
        As[(gcol + 2) * 128 + grow] = pa.z;
        As[(gcol + 3) * 128 + grow] = pa.w;
        Bs[(gcol + 0) * 128 + grow] = pb.x;
        Bs[(gcol + 1) * 128 + grow] = pb.y;
        Bs[(gcol + 2) * 128 + grow] = pb.z;
        Bs[(gcol + 3) * 128 + grow] = pb.w;
        __syncthreads();

        if (kk + 1 < iters) {
            pa = *(const float4*)(ag + (kk + 1) * 8);
            pb = *(const float4*)(bg + (kk + 1) * 8);
        }

        #pragma unroll
        for (int k = 0; k < 8; ++k) {
            float4 a0 = *(const float4*)&As[k * 128 + wm];
            float4 a1 = *(const float4*)&As[k * 128 + wm + 4];
            float4 b0 = *(const float4*)&Bs[k * 128 + wn];
            float4 b1 = *(const float4*)&Bs[k * 128 + wn + 4];

            unsigned long long bp0 = pack2(b0.x, b0.y);
            unsigned long long bp1 = pack2(b0.z, b0.w);
            unsigned long long bp2 = pack2(b1.x, b1.y);
            unsigned long long bp3 = pack2(b1.z, b1.w);

            float av[8] = {a0.x, a0.y, a0.z, a0.w, a1.x, a1.y, a1.z, a1.w};
            #pragma unroll
            for (int i = 0; i < 8; ++i) {
                unsigned long long ap = pack2(av[i], av[i]);
                acc[i][0] = fma2(ap, bp0, acc[i][0]);
                acc[i][1] = fma2(ap, bp1, acc[i][1]);
                acc[i][2] = fma2(ap, bp2, acc[i][2]);
                acc[i][3] = fma2(ap, bp3, acc[i][3]);
            }
        }
        __syncthreads();
    }
}

__device__ __forceinline__ void zero_acc(unsigned long long acc[8][4]) {
    #pragma unroll
    for (int i = 0; i < 8; ++i)
        #pragma unroll
        for (int j = 0; j < 4; ++j)
            acc[i][j] = 0ull;
}

// Epilogue: write acc into [T,B,H] scratch (row m = b*T + t)
__device__ __forceinline__ void write_tbh(unsigned long long acc[8][4],
                                          float* __restrict__ dst,
                                          int m0, int n0)
{
    const int warp = threadIdx.x >> 5, lane = threadIdx.x & 31;
    const int wm = (warp & 1) * 64 + (lane & 7) * 8;
    const int wn = (warp >> 1) * 32 + (lane >> 3) * 8;
    #pragma unroll
    for (int i = 0; i < 8; ++i) {
        const int m = m0 + wm + i;
        const int b = m >> 10;           // / T_
        const int t = m & (T_ - 1);
        float* p = dst + (size_t)t * BH_ + (size_t)b * H_ + n0 + wn;
        float2 v0 = unpack2(acc[i][0]);
        float2 v1 = unpack2(acc[i][1]);
        float2 v2 = unpack2(acc[i][2]);
        float2 v3 = unpack2(acc[i][3]);
        *(float4*)p       = make_float4(v0.x, v0.y, v1.x, v1.y);
        *(float4*)(p + 4) = make_float4(v2.x, v2.y, v3.x, v3.y);
    }
}

// ---------------------------------------------------------------------------
// Kernel 1: dual GEMM (two K-phases sharing one accumulator set).
// ---------------------------------------------------------------------------
__global__ __launch_bounds__(256, 2)
void dual_gemm_kernel(const float* __restrict__ x,
                      const float* __restrict__ w1,
                      const float* __restrict__ w2)
{
    __shared__ float As[8 * 128];
    __shared__ float Bs[8 * 128];

    const int m0 = blockIdx.x * 128;
    const int n0 = blockIdx.y * 128;

    unsigned long long acc[8][4];

    zero_acc(acc);
    sgemm_tile_128(x, D_, 0, m0, w1, HALF_, 0, n0, HALF_, acc, As, Bs);
    write_tbh(acc, g_d1, m0, n0);

    zero_acc(acc);
    sgemm_tile_128(x, D_, HALF_, m0, w2, HALF_, 0, n0, HALF_, acc, As, Bs);
    write_tbh(acc, g_d2, m0, n0);
}

// ---------------------------------------------------------------------------
// Kernel 2: sequential EMA scan over T. One thread per (b,h).
// ---------------------------------------------------------------------------
__global__ __launch_bounds__(256)
void scan_kernel(const float* __restrict__ b1, const float* __restrict__ tau1,
                 const float* __restrict__ b2, const float* __restrict__ tau2)
{
    const int idx = blockIdx.x * blockDim.x + threadIdx.x;   // 0..32767
    const int h   = idx & (H_ - 1);

    const float a1 = 1.0f / (1.0f + __expf(-tau1[h]));
    const float a2 = 1.0f / (1.0f + __expf(-tau2[h]));
    const float c1 = 1.0f - a1;
    const float c2 = 1.0f - a2;
    const float bb1 = b1[h];
    const float bb2 = b2[h];

    float d1 = 0.0f, d2 = 0.0f, mem = 0.0f;

    #pragma unroll 1
    for (int t = 0; t < T_; t += 8) {
        float i1[8], i2[8];
        #pragma unroll
        for (int u = 0; u < 8; ++u) {
            i1[u] = g_d1[(size_t)(t + u) * BH_ + idx];
            i2[u] = g_d2[(size_t)(t + u) * BH_ + idx];
        }
        #pragma unroll
        for (int u = 0; u < 8; ++u) {
            d1  = a1 * d1 + c1 * (i1[u] + bb1);
            d2  = a2 * d2 + c2 * (i2[u] + bb2);
            mem = 0.8f * mem + 0.2f * (d1 + d2);
            g_mems[(size_t)(t + u) * BH_ + idx] = mem;
        }
    }
}

// ---------------------------------------------------------------------------
// Kernel 3: output GEMM + bias + sigmoid.
//   out[b,t,o] = sigmoid( sum_h mems[t,b,h] * wo[o,h] + bo[o] )
// Rows of mems: m = t*B + b.  Tile 128(M) x 128(N=O full width).
// ---------------------------------------------------------------------------
__global__ __launch_bounds__(256, 2)
void out_gemm_kernel(const float* __restrict__ wo,
                     const float* __restrict__ bo,
                     float* __restrict__ out)
{
    __shared__ float As[8 * 128];
    __shared__ float Bs[8 * 128];

    const int m0 = blockIdx.x * 128;

    unsigned long long acc[8][4];
    zero_acc(acc);
    sgemm_tile_128(g_mems, H_, 0, m0, wo, H_, 0, 0, H_, acc, As, Bs);

    const int warp = threadIdx.x >> 5, lane = threadIdx.x & 31;
    const int wm = (warp & 1) * 64 + (lane & 7) * 8;
    const int wn = (warp >> 1) * 32 + (lane >> 3) * 8;

    float4 bo0 = *(const float4*)(bo + wn);
    float4 bo1 = *(const float4*)(bo + wn + 4);

    #pragma unroll
    for (int i = 0; i < 8; ++i) {
        const int m = m0 + wm + i;
        const int t = m >> 6;            // / B_
        const int b = m & (B_ - 1);
        float2 v0 = unpack2(acc[i][0]);
        float2 v1 = unpack2(acc[i][1]);
        float2 v2 = unpack2(acc[i][2]);
        float2 v3 = unpack2(acc[i][3]);
        float v[8] = {v0.x, v0.y, v1.x, v1.y, v2.x, v2.y, v3.x, v3.y};
        float bb[8] = {bo0.x, bo0.y, bo0.z, bo0.w, bo1.x, bo1.y, bo1.z, bo1.w};
        #pragma unroll
        for (int j = 0; j < 8; ++j)
            v[j] = 1.0f / (1.0f + __expf(-(v[j] + bb[j])));
        float* p = out + (size_t)b * (T_ * O_) + (size_t)t * O_ + wn;
        *(float4*)p       = make_float4(v[0], v[1], v[2], v[3]);
        *(float4*)(p + 4) = make_float4(v[4], v[5], v[6], v[7]);
    }
}

// ---------------------------------------------------------------------------
extern "C" void kernel_launch(void* const* d_in, const int* in_sizes, int n_in,
                              void* d_out, int out_size)
{
    const float* x    = (const float*)d_in[0];
    const float* w1   = (const float*)d_in[1];
    const float* b1   = (const float*)d_in[2];
    const float* tau1 = (const float*)d_in[3];
    const float* w2   = (const float*)d_in[4];
    const float* b2   = (const float*)d_in[5];
    const float* tau2 = (const float*)d_in[6];
    const float* wo   = (const float*)d_in[7];
    const float* bo   = (const float*)d_in[8];
    float* out = (float*)d_out;

    dim3 g1(M_ / 128, H_ / 128);          // 512 x 4
    dual_gemm_kernel<<<g1, 256>>>(x, w1, w2);

    scan_kernel<<<BH_ / 256, 256>>>(b1, tau1, b2, tau2);

    dim3 g3(M_ / 128, O_ / 128);          // 512 x 1
    out_gemm_kernel<<<g3, 256>>>(wo, bo, out);
}